// round 3
// baseline (speedup 1.0000x reference)
#include <cuda_runtime.h>
#include <cstdint>

#define W 131072
#define J 21
#define NB 20
#define GRID_BLOCKS ((W * J + 255) / 256)

// weights folded with denominators
#define C_PROJ   (1.0f / 42.0f)    // W_PROJ / (2*J)
#define C_BONE   (1.0f / 20.0f)    // W_BONE / (J-1)
#define C_SMOOTH (0.5f / 63.0f)    // W_SMOOTH / (3*J)
#define C_LIFT   (0.1f / 63.0f)    // W_LIFT / (3*J)

__device__ double g_acc;          // zero-init at load; reset by last block each call
__device__ unsigned int g_count;  // wraps back to 0 via atomicInc

__global__ __launch_bounds__(256)
void loss_kernel(const float* __restrict__ pose,   // [(W+1),3,J]
                 const float* __restrict__ cam,    // [W,2,3]
                 const float* __restrict__ p2d,    // [W,2,J]
                 const float* __restrict__ blen,   // [NB]
                 const float* __restrict__ lift,   // [W,3,NB]
                 const int*   __restrict__ bc,     // [NB,2]
                 const int*   __restrict__ lbc,    // [NB,2]
                 float* __restrict__ out)
{
    const int n = blockIdx.x * blockDim.x + threadIdx.x;
    float acc = 0.0f;

    if (n < W * J) {
        const int w = n / J;
        const int j = n - w * J;

        const float* pf1 = pose + (size_t)(w + 1) * 63;   // frame w+1
        const float x = pf1[j];
        const float y = pf1[21 + j];
        const float z = pf1[42 + j];

        // ---- projection loss ----
        const float* c = cam + (size_t)w * 6;
        const float* q = p2d + (size_t)w * 42;
        float px = c[0] * x + c[1] * y + c[2] * z - q[j];
        float py = c[3] * x + c[4] * y + c[5] * z - q[21 + j];
        acc += C_PROJ * (px * px + py * py);

        // ---- smoothness loss (second difference, t = w, valid for w >= 1) ----
        if (w >= 1) {
            const float* pf0 = pose + (size_t)w * 63;
            const float* pfm = pose + (size_t)(w - 1) * 63;
            float a0 = x            - 2.0f * pf0[j]      + pfm[j];
            float a1 = y            - 2.0f * pf0[21 + j] + pfm[21 + j];
            float a2 = z            - 2.0f * pf0[42 + j] + pfm[42 + j];
            acc += C_SMOOTH * (a0 * a0 + a1 * a1 + a2 * a2);
        }

        // ---- per-bone terms (bone b = j for j < 20) ----
        if (j < NB) {
            const int b = j;

            // bone length loss, frame w+1
            const int ch = bc[2 * b];
            const int pa = bc[2 * b + 1];
            {
                float dx = pf1[ch]      - pf1[pa];
                float dy = pf1[21 + ch] - pf1[21 + pa];
                float dz = pf1[42 + ch] - pf1[42 + pa];
                float len = dx * dx + dy * dy + dz * dz;
                float e = len - blen[b];
                acc += C_BONE * e * e;
            }
            // bone length loss, frame 0 (done once, by the w==0 threads)
            if (w == 0) {
                const float* p0 = pose;
                float dx = p0[ch]      - p0[pa];
                float dy = p0[21 + ch] - p0[21 + pa];
                float dz = p0[42 + ch] - p0[42 + pa];
                float len = dx * dx + dy * dy + dz * dz;
                float e = len - blen[b];
                acc += C_BONE * e * e;
            }

            // lift direction loss (frames 1..W -> pf1)
            const int lch = lbc[2 * b];
            const int lpa = lbc[2 * b + 1];
            float bx = pf1[lch]      - pf1[lpa];
            float by = pf1[21 + lch] - pf1[21 + lpa];
            float bz = pf1[42 + lch] - pf1[42 + lpa];
            float inv = 1.0f / sqrtf(bx * bx + by * by + bz * bz);
            const float* ld = lift + (size_t)w * 60;
            float ex = ld[b]      - bx * inv;
            float ey = ld[20 + b] - by * inv;
            float ez = ld[40 + b] - bz * inv;
            acc += C_LIFT * (ex * ex + ey * ey + ez * ez);
        }
    }

    // ---- reduction: warp shuffle -> smem -> block sum -> double atomic ----
    #pragma unroll
    for (int off = 16; off > 0; off >>= 1)
        acc += __shfl_down_sync(0xFFFFFFFFu, acc, off);

    __shared__ float warp_sums[8];
    __shared__ bool is_last;
    const int lane = threadIdx.x & 31;
    const int wid  = threadIdx.x >> 5;
    if (lane == 0) warp_sums[wid] = acc;
    __syncthreads();

    if (wid == 0) {
        float v = (lane < 8) ? warp_sums[lane] : 0.0f;
        #pragma unroll
        for (int off = 4; off > 0; off >>= 1)
            v += __shfl_down_sync(0xFFFFFFFFu, v, off);
        if (lane == 0) {
            atomicAdd(&g_acc, (double)v);
            __threadfence();
            unsigned int ticket = atomicInc(&g_count, GRID_BLOCKS - 1);
            is_last = (ticket == GRID_BLOCKS - 1);
        }
    }
    __syncthreads();

    // last block to finish: publish result and reset accumulator for next replay
    if (is_last && threadIdx.x == 0) {
        __threadfence();
        out[0] = (float)g_acc;
        g_acc = 0.0;   // g_count already wrapped to 0 via atomicInc
        __threadfence();
    }
}

extern "C" void kernel_launch(void* const* d_in, const int* in_sizes, int n_in,
                              void* d_out, int out_size)
{
    const float* pose = (const float*)d_in[0];
    const float* cam  = (const float*)d_in[1];
    const float* p2d  = (const float*)d_in[2];
    const float* blen = (const float*)d_in[3];
    const float* lift = (const float*)d_in[4];
    const int*   bc   = (const int*)d_in[5];
    const int*   lbc  = (const int*)d_in[6];
    float* out = (float*)d_out;

    loss_kernel<<<GRID_BLOCKS, 256>>>(pose, cam, p2d, blen, lift, bc, lbc, out);
}

// round 4
// speedup vs baseline: 1.0617x; 1.0617x over previous
#include <cuda_runtime.h>
#include <cstdint>

#define W 131072
#define J 21
#define NB 20
#define F 24                               // frames per block
#define NBLK ((W + F - 1) / F)             // 5462
#define ITEMS (F * J)                      // 504 work items per block

// weights folded with denominators
#define C_PROJ   (1.0f / 42.0f)    // W_PROJ / (2*J)
#define C_BONE   (1.0f / 20.0f)    // W_BONE / (J-1)
#define C_SMOOTH (0.5f / 63.0f)    // W_SMOOTH / (3*J)
#define C_LIFT   (0.1f / 63.0f)    // W_LIFT / (3*J)

__device__ float g_partial[NBLK];

__global__ __launch_bounds__(256)
void loss_kernel(const float* __restrict__ pose,   // [(W+1),3,J]
                 const float* __restrict__ cam,    // [W,2,3]
                 const float* __restrict__ p2d,    // [W,2,J]
                 const float* __restrict__ blen,   // [NB]
                 const float* __restrict__ lift,   // [W,3,NB]
                 const int*   __restrict__ bc,     // [NB,2]
                 const int*   __restrict__ lbc)    // [NB,2]
{
    __shared__ float s_pose[(F + 2) * 63];   // pose frames [wbase-1 .. wbase+F]
    __shared__ float s_cam[F * 6];
    __shared__ int   s_bc[2 * NB];
    __shared__ int   s_lbc[2 * NB];
    __shared__ float s_blen[NB];
    __shared__ float warp_sums[8];

    const int tid   = threadIdx.x;
    const int wbase = blockIdx.x * F;
    const int p0    = wbase - 1;             // first staged pose frame (may be -1)

    // ---- stage pose frames (coalesced) ----
    {
        const int base_g = p0 * 63;
        #pragma unroll
        for (int i = tid; i < (F + 2) * 63; i += 256) {
            const int g = base_g + i;
            s_pose[i] = (g >= 0 && g < (W + 1) * 63) ? pose[g] : 0.0f;
        }
    }
    // ---- stage cam ----
    for (int i = tid; i < F * 6; i += 256) {
        const int g = wbase * 6 + i;
        s_cam[i] = (g < W * 6) ? cam[g] : 0.0f;
    }
    // ---- stage tiny tables ----
    if (tid < 2 * NB)                 s_bc[tid]        = bc[tid];
    else if (tid >= 64 && tid < 104)  s_lbc[tid - 64]  = lbc[tid - 64];
    else if (tid >= 128 && tid < 148) s_blen[tid - 128] = blen[tid - 128];
    __syncthreads();

    float acc = 0.0f;

    #pragma unroll
    for (int rep = 0; rep < 2; rep++) {
        const int item = tid + rep * 256;
        if (item >= ITEMS) break;
        const int wl = item / 21;
        const int j  = item - wl * 21;
        const int w  = wbase + wl;
        if (w >= W) continue;

        const float* pf1 = s_pose + (wl + 2) * 63;     // pose frame w+1
        const float x = pf1[j];
        const float y = pf1[21 + j];
        const float z = pf1[42 + j];

        // ---- projection loss ----
        const float* c = s_cam + wl * 6;
        const float* q = p2d + (size_t)w * 42;
        float px = c[0] * x + c[1] * y + c[2] * z - q[j];
        float py = c[3] * x + c[4] * y + c[5] * z - q[21 + j];
        acc += C_PROJ * (px * px + py * py);

        // ---- smoothness (second difference), valid for w >= 1 ----
        if (w >= 1) {
            const float* pf0 = s_pose + (wl + 1) * 63;  // frame w
            const float* pfm = s_pose + wl * 63;        // frame w-1
            float a0 = x - 2.0f * pf0[j]      + pfm[j];
            float a1 = y - 2.0f * pf0[21 + j] + pfm[21 + j];
            float a2 = z - 2.0f * pf0[42 + j] + pfm[42 + j];
            acc += C_SMOOTH * (a0 * a0 + a1 * a1 + a2 * a2);
        }

        // ---- per-bone terms (bone b = j for j < NB) ----
        if (j < NB) {
            const int ch = s_bc[2 * j];
            const int pa = s_bc[2 * j + 1];
            {
                float dx = pf1[ch]      - pf1[pa];
                float dy = pf1[21 + ch] - pf1[21 + pa];
                float dz = pf1[42 + ch] - pf1[42 + pa];
                float len = dx * dx + dy * dy + dz * dz;
                float e = len - s_blen[j];
                acc += C_BONE * e * e;
            }
            // bone length loss, pose frame 0 (done once, by w==0 threads; slot 1)
            if (w == 0) {
                const float* pz = s_pose + 63;          // pose frame 0
                float dx = pz[ch]      - pz[pa];
                float dy = pz[21 + ch] - pz[21 + pa];
                float dz = pz[42 + ch] - pz[42 + pa];
                float len = dx * dx + dy * dy + dz * dz;
                float e = len - s_blen[j];
                acc += C_BONE * e * e;
            }

            // lift direction loss
            const int lch = s_lbc[2 * j];
            const int lpa = s_lbc[2 * j + 1];
            float bx = pf1[lch]      - pf1[lpa];
            float by = pf1[21 + lch] - pf1[21 + lpa];
            float bz = pf1[42 + lch] - pf1[42 + lpa];
            float inv = 1.0f / sqrtf(bx * bx + by * by + bz * bz);
            const float* ld = lift + (size_t)w * 60;
            float ex = ld[j]      - bx * inv;
            float ey = ld[20 + j] - by * inv;
            float ez = ld[40 + j] - bz * inv;
            acc += C_LIFT * (ex * ex + ey * ey + ez * ez);
        }
    }

    // ---- block reduction ----
    #pragma unroll
    for (int off = 16; off > 0; off >>= 1)
        acc += __shfl_down_sync(0xFFFFFFFFu, acc, off);

    const int lane = tid & 31;
    const int wid  = tid >> 5;
    if (lane == 0) warp_sums[wid] = acc;
    __syncthreads();

    if (wid == 0) {
        float v = (lane < 8) ? warp_sums[lane] : 0.0f;
        #pragma unroll
        for (int off = 4; off > 0; off >>= 1)
            v += __shfl_down_sync(0xFFFFFFFFu, v, off);
        if (lane == 0)
            g_partial[blockIdx.x] = v;
    }
}

__global__ __launch_bounds__(256)
void finalize_kernel(float* __restrict__ out)
{
    __shared__ double warp_sums[8];
    const int tid = threadIdx.x;

    double s = 0.0;
    for (int i = tid; i < NBLK; i += 256)
        s += (double)g_partial[i];

    #pragma unroll
    for (int off = 16; off > 0; off >>= 1)
        s += __shfl_down_sync(0xFFFFFFFFu, s, off);

    const int lane = tid & 31;
    const int wid  = tid >> 5;
    if (lane == 0) warp_sums[wid] = s;
    __syncthreads();

    if (wid == 0) {
        double v = (lane < 8) ? warp_sums[lane] : 0.0;
        #pragma unroll
        for (int off = 4; off > 0; off >>= 1)
            v += __shfl_down_sync(0xFFFFFFFFu, v, off);
        if (lane == 0) out[0] = (float)v;
    }
}

extern "C" void kernel_launch(void* const* d_in, const int* in_sizes, int n_in,
                              void* d_out, int out_size)
{
    const float* pose = (const float*)d_in[0];
    const float* cam  = (const float*)d_in[1];
    const float* p2d  = (const float*)d_in[2];
    const float* blen = (const float*)d_in[3];
    const float* lift = (const float*)d_in[4];
    const int*   bc   = (const int*)d_in[5];
    const int*   lbc  = (const int*)d_in[6];
    float* out = (float*)d_out;

    loss_kernel<<<NBLK, 256>>>(pose, cam, p2d, blen, lift, bc, lbc);
    finalize_kernel<<<1, 256>>>(out);
}

// round 5
// speedup vs baseline: 1.1823x; 1.1135x over previous
#include <cuda_runtime.h>
#include <cstdint>

#define W 131072
#define J 21
#define NB 20
#define F 24                               // frames per tile
#define NT ((W + F - 1) / F)               // 5462 tiles
#define GRID 1184                          // persistent blocks (8 per SM)
#define ITEMS (F * J)                      // 504 work items per tile

// weights folded with denominators
#define C_PROJ   (1.0f / 42.0f)    // W_PROJ / (2*J)
#define C_BONE   (1.0f / 20.0f)    // W_BONE / (J-1)
#define C_SMOOTH (0.5f / 63.0f)    // W_SMOOTH / (3*J)
#define C_LIFT   (0.1f / 63.0f)    // W_LIFT / (3*J)

__device__ double g_acc;           // zero at load; last block resets each call
__device__ unsigned int g_count;   // wraps to 0 via atomicInc

__global__ __launch_bounds__(256)
void loss_kernel(const float* __restrict__ pose,   // [(W+1),3,J]
                 const float* __restrict__ cam,    // [W,2,3]
                 const float* __restrict__ p2d,    // [W,2,J]
                 const float* __restrict__ blen,   // [NB]
                 const float* __restrict__ lift,   // [W,3,NB]
                 const int*   __restrict__ bc,     // [NB,2]
                 const int*   __restrict__ lbc,    // [NB,2]
                 float* __restrict__ out)
{
    __shared__ float s_pose[(F + 2) * 63];   // pose frames [wbase-1 .. wbase+F]
    __shared__ float s_cam[F * 6];
    __shared__ int   s_bc[2 * NB];
    __shared__ int   s_lbc[2 * NB];
    __shared__ float s_blen[NB];
    __shared__ float warp_sums[8];
    __shared__ bool  is_last;

    const int tid = threadIdx.x;

    // tiny tables once per block
    if (tid < 2 * NB)                 s_bc[tid]         = bc[tid];
    else if (tid >= 64 && tid < 104)  s_lbc[tid - 64]   = lbc[tid - 64];
    else if (tid >= 128 && tid < 148) s_blen[tid - 128] = blen[tid - 128];

    float acc = 0.0f;

    for (int tile = blockIdx.x; tile < NT; tile += GRID) {
        const int wbase = tile * F;

        __syncthreads();   // protect s_pose/s_cam from previous iteration's readers

        // ---- stage pose frames wbase-1 .. wbase+F (coalesced, clamped) ----
        {
            const int base_g = (wbase - 1) * 63;
            const int g_max  = (W + 1) * 63 - 1;
            #pragma unroll
            for (int i = tid; i < (F + 2) * 63; i += 256) {
                int g = base_g + i;
                g = g < 0 ? 0 : (g > g_max ? g_max : g);
                s_pose[i] = pose[g];
            }
        }
        // ---- stage cam ----
        {
            const int g_max = W * 6 - 1;
            #pragma unroll
            for (int i = tid; i < F * 6; i += 256) {
                int g = wbase * 6 + i;
                g = g > g_max ? g_max : g;
                s_cam[i] = cam[g];
            }
        }
        __syncthreads();

        #pragma unroll
        for (int rep = 0; rep < 2; rep++) {
            const int item = tid + rep * 256;
            if (item >= ITEMS) break;
            const int wl = item / 21;
            const int j  = item - wl * 21;
            const int w  = wbase + wl;
            if (w >= W) continue;

            const float* pf1 = s_pose + (wl + 2) * 63;     // pose frame w+1
            const float x = pf1[j];
            const float y = pf1[21 + j];
            const float z = pf1[42 + j];

            // ---- projection loss ----
            const float* c = s_cam + wl * 6;
            const float* q = p2d + (size_t)w * 42;
            float px = c[0] * x + c[1] * y + c[2] * z - q[j];
            float py = c[3] * x + c[4] * y + c[5] * z - q[21 + j];
            acc += C_PROJ * (px * px + py * py);

            // ---- smoothness (second difference), valid for w >= 1 ----
            if (w >= 1) {
                const float* pf0 = s_pose + (wl + 1) * 63;  // frame w
                const float* pfm = s_pose + wl * 63;        // frame w-1
                float a0 = x - 2.0f * pf0[j]      + pfm[j];
                float a1 = y - 2.0f * pf0[21 + j] + pfm[21 + j];
                float a2 = z - 2.0f * pf0[42 + j] + pfm[42 + j];
                acc += C_SMOOTH * (a0 * a0 + a1 * a1 + a2 * a2);
            }

            // ---- per-bone terms (bone b = j for j < NB) ----
            if (j < NB) {
                const int ch = s_bc[2 * j];
                const int pa = s_bc[2 * j + 1];
                {
                    float dx = pf1[ch]      - pf1[pa];
                    float dy = pf1[21 + ch] - pf1[21 + pa];
                    float dz = pf1[42 + ch] - pf1[42 + pa];
                    float len = dx * dx + dy * dy + dz * dz;
                    float e = len - s_blen[j];
                    acc += C_BONE * e * e;
                }
                // bone length term for pose frame 0 (once, by w==0 threads)
                if (w == 0) {
                    const float* pz = s_pose + 63;          // pose frame 0
                    float dx = pz[ch]      - pz[pa];
                    float dy = pz[21 + ch] - pz[21 + pa];
                    float dz = pz[42 + ch] - pz[42 + pa];
                    float len = dx * dx + dy * dy + dz * dz;
                    float e = len - s_blen[j];
                    acc += C_BONE * e * e;
                }

                // lift direction loss
                const int lch = s_lbc[2 * j];
                const int lpa = s_lbc[2 * j + 1];
                float bx = pf1[lch]      - pf1[lpa];
                float by = pf1[21 + lch] - pf1[21 + lpa];
                float bz = pf1[42 + lch] - pf1[42 + lpa];
                float inv = 1.0f / sqrtf(bx * bx + by * by + bz * bz);
                const float* ld = lift + (size_t)w * 60;
                float ex = ld[j]      - bx * inv;
                float ey = ld[20 + j] - by * inv;
                float ez = ld[40 + j] - bz * inv;
                acc += C_LIFT * (ex * ex + ey * ey + ez * ez);
            }
        }
    }

    // ---- block reduction ----
    #pragma unroll
    for (int off = 16; off > 0; off >>= 1)
        acc += __shfl_down_sync(0xFFFFFFFFu, acc, off);

    const int lane = tid & 31;
    const int wid  = tid >> 5;
    if (lane == 0) warp_sums[wid] = acc;
    __syncthreads();

    if (wid == 0) {
        float v = (lane < 8) ? warp_sums[lane] : 0.0f;
        #pragma unroll
        for (int off = 4; off > 0; off >>= 1)
            v += __shfl_down_sync(0xFFFFFFFFu, v, off);
        if (lane == 0) {
            atomicAdd(&g_acc, (double)v);
            __threadfence();
            unsigned int ticket = atomicInc(&g_count, GRID - 1);
            is_last = (ticket == GRID - 1);
        }
    }
    __syncthreads();

    if (is_last && tid == 0) {
        __threadfence();
        out[0] = (float)g_acc;
        g_acc = 0.0;      // reset for next graph replay (g_count wrapped already)
        __threadfence();
    }
}

extern "C" void kernel_launch(void* const* d_in, const int* in_sizes, int n_in,
                              void* d_out, int out_size)
{
    const float* pose = (const float*)d_in[0];
    const float* cam  = (const float*)d_in[1];
    const float* p2d  = (const float*)d_in[2];
    const float* blen = (const float*)d_in[3];
    const float* lift = (const float*)d_in[4];
    const int*   bc   = (const int*)d_in[5];
    const int*   lbc  = (const int*)d_in[6];
    float* out = (float*)d_out;

    loss_kernel<<<GRID, 256>>>(pose, cam, p2d, blen, lift, bc, lbc, out);
}

// round 6
// speedup vs baseline: 1.2243x; 1.0356x over previous
#include <cuda_runtime.h>
#include <cstdint>

#define W 131072
#define J 21
#define NB 20
#define BLOCK 256
#define GRID 1024
#define WPB (BLOCK / 32)
#define NWARP (GRID * WPB)                 // 8192 warps
#define CHUNK ((W + NWARP - 1) / NWARP)    // 16 frames per warp (exact)

// weights folded with denominators
#define C_PROJ   (1.0f / 42.0f)    // W_PROJ / (2*J)
#define C_BONE   (1.0f / 20.0f)    // W_BONE / (J-1)
#define C_SMOOTH (0.5f / 63.0f)    // W_SMOOTH / (3*J)
#define C_LIFT   (0.1f / 63.0f)    // W_LIFT / (3*J)

#define FULL 0xFFFFFFFFu

__device__ double g_acc;           // zero at load; last block resets each call
__device__ unsigned int g_count;   // wraps to 0 via atomicInc

__global__ __launch_bounds__(BLOCK)
void loss_kernel(const float* __restrict__ pose,   // [(W+1),3,J]
                 const float* __restrict__ cam,    // [W,2,3]
                 const float* __restrict__ p2d,    // [W,2,J]
                 const float* __restrict__ blen,   // [NB]
                 const float* __restrict__ lift,   // [W,3,NB]
                 const int*   __restrict__ bc,     // [NB,2]
                 const int*   __restrict__ lbc,    // [NB,2]
                 float* __restrict__ out)
{
    const int tid  = threadIdx.x;
    const int lane = tid & 31;
    const int wid  = tid >> 5;
    const int gw   = blockIdx.x * WPB + wid;
    const int f0   = gw * CHUNK;

    const bool jok = lane < J;     // joint-valid lanes
    const bool bok = lane < NB;    // bone-valid lanes

    // per-lane bone tables (read once, kept in registers)
    int ch = 0, pa = 0, lch = 0, lpa = 0;
    float bl = 0.0f;
    if (bok) {
        ch  = bc[2 * lane];
        pa  = bc[2 * lane + 1];
        lch = lbc[2 * lane];
        lpa = lbc[2 * lane + 1];
        bl  = blen[lane];
    }

    float acc = 0.0f;

    if (f0 < W) {
        const int fend = min(W, f0 + CHUNK);

        // ---- lead-in: p0 = pose frame f0, pm = pose frame max(f0-1,0) ----
        const float* pA = pose + (size_t)f0 * 63;
        float x0 = jok ? pA[lane]          : 0.0f;
        float y0 = jok ? pA[J + lane]      : 0.0f;
        float z0 = jok ? pA[2 * J + lane]  : 0.0f;
        const float* pB = pose + (size_t)(f0 > 0 ? f0 - 1 : 0) * 63;
        float xm = jok ? pB[lane]          : 0.0f;
        float ym = jok ? pB[J + lane]      : 0.0f;
        float zm = jok ? pB[2 * J + lane]  : 0.0f;

        // ---- frame-0 bone term (owned by the warp whose chunk starts at 0) ----
        if (f0 == 0) {
            float dx = __shfl_sync(FULL, x0, ch) - __shfl_sync(FULL, x0, pa);
            float dy = __shfl_sync(FULL, y0, ch) - __shfl_sync(FULL, y0, pa);
            float dz = __shfl_sync(FULL, z0, ch) - __shfl_sync(FULL, z0, pa);
            float len = dx * dx + dy * dy + dz * dz;
            float e = len - bl;
            if (bok) acc += C_BONE * e * e;
        }

        for (int w = f0; w < fend; w++) {
            // ---- load frame w+1 (the only pose DRAM read per iteration) ----
            const float* pf = pose + (size_t)(w + 1) * 63;
            float x1 = jok ? pf[lane]         : 0.0f;
            float y1 = jok ? pf[J + lane]     : 0.0f;
            float z1 = jok ? pf[2 * J + lane] : 0.0f;

            const float* c = cam + (size_t)w * 6;       // uniform broadcasts
            float c0 = c[0], c1 = c[1], c2 = c[2];
            float c3 = c[3], c4 = c[4], c5 = c[5];

            const float* q = p2d + (size_t)w * 42;
            float qx = jok ? q[lane]     : 0.0f;
            float qy = jok ? q[J + lane] : 0.0f;

            const float* ld = lift + (size_t)w * 60;
            float ldx = bok ? ld[lane]          : 0.0f;
            float ldy = bok ? ld[NB + lane]     : 0.0f;
            float ldz = bok ? ld[2 * NB + lane] : 0.0f;

            // ---- projection ----
            float px = c0 * x1 + c1 * y1 + c2 * z1 - qx;
            float py = c3 * x1 + c4 * y1 + c5 * z1 - qy;
            if (jok) acc += C_PROJ * (px * px + py * py);

            // ---- smoothness (second difference), valid for w >= 1 ----
            if (w >= 1) {
                float a0 = x1 - 2.0f * x0 + xm;
                float a1 = y1 - 2.0f * y0 + ym;
                float a2 = z1 - 2.0f * z0 + zm;
                if (jok) acc += C_SMOOTH * (a0 * a0 + a1 * a1 + a2 * a2);
            }

            // ---- bone length (frame w+1), via warp shuffles ----
            float bx = __shfl_sync(FULL, x1, ch) - __shfl_sync(FULL, x1, pa);
            float by = __shfl_sync(FULL, y1, ch) - __shfl_sync(FULL, y1, pa);
            float bz = __shfl_sync(FULL, z1, ch) - __shfl_sync(FULL, z1, pa);
            {
                float len = bx * bx + by * by + bz * bz;
                float e = len - bl;
                if (bok) acc += C_BONE * e * e;
            }

            // ---- lift direction ----
            float ux = __shfl_sync(FULL, x1, lch) - __shfl_sync(FULL, x1, lpa);
            float uy = __shfl_sync(FULL, y1, lch) - __shfl_sync(FULL, y1, lpa);
            float uz = __shfl_sync(FULL, z1, lch) - __shfl_sync(FULL, z1, lpa);
            {
                float n2 = ux * ux + uy * uy + uz * uz;
                float inv = bok ? (1.0f / sqrtf(n2)) : 0.0f;
                float ex = ldx - ux * inv;
                float ey = ldy - uy * inv;
                float ez = ldz - uz * inv;
                if (bok) acc += C_LIFT * (ex * ex + ey * ey + ez * ez);
            }

            // rotate frame registers
            xm = x0; ym = y0; zm = z0;
            x0 = x1; y0 = y1; z0 = z1;
        }
    }

    // ---- warp reduction ----
    #pragma unroll
    for (int off = 16; off > 0; off >>= 1)
        acc += __shfl_down_sync(FULL, acc, off);

    __shared__ float warp_sums[WPB];
    __shared__ bool  is_last;
    if (lane == 0) warp_sums[wid] = acc;
    __syncthreads();

    if (wid == 0) {
        float v = (lane < WPB) ? warp_sums[lane] : 0.0f;
        #pragma unroll
        for (int off = 4; off > 0; off >>= 1)
            v += __shfl_down_sync(FULL, v, off);
        if (lane == 0) {
            atomicAdd(&g_acc, (double)v);
            __threadfence();
            unsigned int ticket = atomicInc(&g_count, GRID - 1);
            is_last = (ticket == GRID - 1);
        }
    }
    __syncthreads();

    if (is_last && tid == 0) {
        __threadfence();
        out[0] = (float)g_acc;
        g_acc = 0.0;   // reset for next graph replay (g_count already wrapped)
        __threadfence();
    }
}

extern "C" void kernel_launch(void* const* d_in, const int* in_sizes, int n_in,
                              void* d_out, int out_size)
{
    const float* pose = (const float*)d_in[0];
    const float* cam  = (const float*)d_in[1];
    const float* p2d  = (const float*)d_in[2];
    const float* blen = (const float*)d_in[3];
    const float* lift = (const float*)d_in[4];
    const int*   bc   = (const int*)d_in[5];
    const int*   lbc  = (const int*)d_in[6];
    float* out = (float*)d_out;

    loss_kernel<<<GRID, BLOCK>>>(pose, cam, p2d, blen, lift, bc, lbc, out);
}